// round 15
// baseline (speedup 1.0000x reference)
#include <cuda_runtime.h>
#include <cstdint>

// ===========================================================================
// reinforce_cons_loss (2-kernel pipeline) — converged design:
//   K1 Threefry-2x32 Gumbel-max categorical sampling (at alu-pipe floor)
//   K2 (512 thr/CTA) per-(task,class): fg bitset; in-CTA 5x5-count argmax
//      seed (bit-plane CSA, 1 row/thread); flood fill on WARP 0 ONLY —
//      barrier-free H-closure iterations (ballot convergence, redux bbox),
//      row+col bbox restriction, 4-word narrow fast path; division-free
//      log-prob tail; last-CTA final loss reduction.
// ===========================================================================

#define NIMG   4
#define NSAMP  10
#define HH     512
#define WW     512
#define NTASK  (NIMG*NSAMP)
#define NPIX   (HH*WW)                 // 1<<18
#define TOTPIX ((unsigned)NTASK*NPIX)  // 10485760
#define PITCH  17
#define FT     512

__device__ uint8_t g_cls[(size_t)NTASK * NPIX];
__device__ double  g_partial[NTASK * 3];
__device__ int     g_done;

// ---------------------------------------------------------------------------
// Threefry-2x32, 20 rounds, key (0,42), counter (0, idx); out = x0 ^ x1
// ---------------------------------------------------------------------------
#define TF_ROUND(x0,x1,R) { x0 += x1; x1 = __funnelshift_l(x1, x1, (R)); x1 ^= x0; }

__device__ __forceinline__ uint32_t gumbel_bits(uint32_t idx) {
    const uint32_t k0 = 0u, k1 = 42u;
    const uint32_t k2 = k0 ^ k1 ^ 0x1BD11BDAu;
    uint32_t x0 = k0, x1 = idx + k1;
    TF_ROUND(x0,x1,13) TF_ROUND(x0,x1,15) TF_ROUND(x0,x1,26) TF_ROUND(x0,x1,6)
    x0 += k1; x1 += k2 + 1u;
    TF_ROUND(x0,x1,17) TF_ROUND(x0,x1,29) TF_ROUND(x0,x1,16) TF_ROUND(x0,x1,24)
    x0 += k2; x1 += k0 + 2u;
    TF_ROUND(x0,x1,13) TF_ROUND(x0,x1,15) TF_ROUND(x0,x1,26) TF_ROUND(x0,x1,6)
    x0 += k0; x1 += k1 + 3u;
    TF_ROUND(x0,x1,17) TF_ROUND(x0,x1,29) TF_ROUND(x0,x1,16) TF_ROUND(x0,x1,24)
    x0 += k1; x1 += k2 + 4u;
    TF_ROUND(x0,x1,13) TF_ROUND(x0,x1,15) TF_ROUND(x0,x1,26) TF_ROUND(x0,x1,6)
    x0 += k2; x1 += k0 + 5u;
    return x0 ^ x1;
}

__device__ __forceinline__ float bits_to_u(uint32_t bits) {
    const float tiny = 1.17549435082228751e-38f;
    float f = __uint_as_float(__umulhi(bits, 0x00800000u) + 0x3f800000u) - 1.0f;
    return fmaxf(f, tiny);
}

// ---------------------------------------------------------------------------
// K1: gumbel-max, product form argmax_c p_c / (-log2 u_c); MUFU fast path
//     with precise-log fallback on near-ties.
// ---------------------------------------------------------------------------
__global__ void __launch_bounds__(256) k_sample(const float* __restrict__ preds) {
    unsigned gid = blockIdx.x * 256u + threadIdx.x;
    if (blockIdx.x == 0 && threadIdx.x == 0) g_done = 0;
    if (gid >= TOTPIX) return;
    unsigned hw = gid & 0x3FFFFu;
    unsigned n  = (gid >> 18) & 3u;
    const float* pb = preds + ((size_t)n << 20) + hw;

    float p0 = pb[0];
    float p1 = pb[(size_t)1 << 18];
    float p2 = pb[(size_t)2 << 18];
    float p3 = pb[(size_t)3 << 18];

    unsigned base = gid << 2;
    float u0 = bits_to_u(gumbel_bits(base + 0));
    float u1 = bits_to_u(gumbel_bits(base + 1));
    float u2 = bits_to_u(gumbel_bits(base + 2));
    float u3 = bits_to_u(gumbel_bits(base + 3));

    float w0 = -__log2f(u0);
    float w1 = -__log2f(u1);
    float w2 = -__log2f(u2);
    float w3 = -__log2f(u3);

    float bp = p0, bw = w0; unsigned bc = 0;
    bool risky = false;
    {
        float lhs = p1 * bw, rhs = bp * w1;
        risky |= fabsf(lhs - rhs) <= 2e-6f + 2e-6f * (lhs + rhs);
        if (lhs > rhs) { bp = p1; bw = w1; bc = 1; }
    }
    {
        float lhs = p2 * bw, rhs = bp * w2;
        risky |= fabsf(lhs - rhs) <= 2e-6f + 2e-6f * (lhs + rhs);
        if (lhs > rhs) { bp = p2; bw = w2; bc = 2; }
    }
    {
        float lhs = p3 * bw, rhs = bp * w3;
        risky |= fabsf(lhs - rhs) <= 2e-6f + 2e-6f * (lhs + rhs);
        if (lhs > rhs) { bp = p3; bw = w3; bc = 3; }
    }
    if (risky) {
        w0 = -log2f(u0);
        w1 = -log2f(u1);
        w2 = -log2f(u2);
        w3 = -log2f(u3);
        bp = p0; bw = w0; bc = 0;
        if (p1 * bw > bp * w1) { bp = p1; bw = w1; bc = 1; }
        if (p2 * bw > bp * w2) { bp = p2; bw = w2; bc = 2; }
        if (p3 * bw > bp * w3) { bp = p3; bw = w3; bc = 3; }
    }
    g_cls[gid] = (uint8_t)bc;
}

// ---------------------------------------------------------------------------
// K2 helpers
// ---------------------------------------------------------------------------
__device__ __forceinline__ uint32_t word_closure(uint32_t g, uint32_t s) {
    uint32_t up = g & ~(g + s);
    uint32_t gr = __brev(g), sr = __brev(s);
    uint32_t dn = __brev(gr & ~(gr + sr));
    return s | up | dn;
}

__device__ __forceinline__ uint32_t nib4(uint32_t v, uint32_t cpat) {
    uint32_t eq = __vcmpeq4(v, cpat);
    return ((eq & 0x01010101u) * 0x01020408u) >> 24;
}

__device__ __forceinline__ uint32_t maj3(uint32_t a, uint32_t b, uint32_t c) {
    return (a & b) | (a & c) | (b & c);
}

__device__ __forceinline__ void hwin_argmax(
        uint32_t P0p, uint32_t P0c, uint32_t P0n,
        uint32_t P1p, uint32_t P1c, uint32_t P1n,
        uint32_t P2p, uint32_t P2c, uint32_t P2n,
        uint32_t m, int r, int j, unsigned long long& mykey) {
    if (!m) return;
    uint32_t n1_0 = __funnelshift_l(P0p, P0c, 2);
    uint32_t n1_1 = __funnelshift_l(P1p, P1c, 2);
    uint32_t n1_2 = __funnelshift_l(P2p, P2c, 2);
    uint32_t n2_0 = __funnelshift_l(P0p, P0c, 1);
    uint32_t n2_1 = __funnelshift_l(P1p, P1c, 1);
    uint32_t n2_2 = __funnelshift_l(P2p, P2c, 1);
    uint32_t n4_0 = __funnelshift_r(P0c, P0n, 1);
    uint32_t n4_1 = __funnelshift_r(P1c, P1n, 1);
    uint32_t n4_2 = __funnelshift_r(P2c, P2n, 1);
    uint32_t n5_0 = __funnelshift_r(P0c, P0n, 2);
    uint32_t n5_1 = __funnelshift_r(P1c, P1n, 2);
    uint32_t n5_2 = __funnelshift_r(P2c, P2n, 2);
    uint32_t s0 = n1_0 ^ n2_0 ^ P0c, a1 = maj3(n1_0, n2_0, P0c);
    uint32_t s1 = n1_1 ^ n2_1 ^ P1c, a2 = maj3(n1_1, n2_1, P1c);
    uint32_t s2 = n1_2 ^ n2_2 ^ P2c, a3 = maj3(n1_2, n2_2, P2c);
    uint32_t t0 = s0 ^ n4_0,         c1a = s0 & n4_0;
    uint32_t t1 = s1 ^ a1 ^ n4_1,    c2a = maj3(s1, a1, n4_1);
    uint32_t t2 = s2 ^ a2 ^ n4_2,    c3a = maj3(s2, a2, n4_2);
    uint32_t t3 = a3;
    uint32_t u0 = t0 ^ n5_0,         d1 = t0 & n5_0;
    uint32_t u1 = t1 ^ c1a ^ n5_1,   d2 = maj3(t1, c1a, n5_1);
    uint32_t u2 = t2 ^ c2a ^ n5_2,   d3 = maj3(t2, c2a, n5_2);
    uint32_t u3 = t3 ^ c3a,          d4 = t3 & c3a;
    uint32_t H0 = u0;
    uint32_t H1 = u1 ^ d1,           e1 = u1 & d1;
    uint32_t H2 = u2 ^ d2 ^ e1,      e2 = maj3(u2, d2, e1);
    uint32_t H3 = u3 ^ d3 ^ e2,      e3 = maj3(u3, d3, e2);
    uint32_t H4 = d4 ^ e3;
    uint32_t M = 0, tt;
    tt = m & H4; if (tt) { m = tt; M += 16u; }
    tt = m & H3; if (tt) { m = tt; M += 8u; }
    tt = m & H2; if (tt) { m = tt; M += 4u; }
    tt = m & H1; if (tt) { m = tt; M += 2u; }
    tt = m & H0; if (tt) { m = tt; M += 1u; }
    unsigned idx = ((unsigned)r << 9) | ((unsigned)j << 5)
                 | (unsigned)(__ffs(m) - 1);
    unsigned long long key = ((unsigned long long)M << 18) |
                             (unsigned long long)(0x3FFFFu - idx);
    if (key > mykey) mykey = key;
}

// ---------------------------------------------------------------------------
// K2: one CTA (512 thr) per (task, class).
// ---------------------------------------------------------------------------
__global__ void __launch_bounds__(FT) k_flood(const float* __restrict__ preds,
                                              float* __restrict__ out) {
    extern __shared__ uint32_t sm[];
    uint32_t* fg = sm;                 // 512*17 words
    uint32_t* fl = sm + 512 * PITCH;   // 512*17 words
    __shared__ int s_r0, s_r1, s_c0, s_c1;
    __shared__ double s_red[FT / 32];
    __shared__ int s_last;
    __shared__ unsigned long long s_bestkey;

    int tid  = threadIdx.x;
    int task = blockIdx.x;
    int t = task / 3;
    int c = task % 3 + 1;
    int n = t & 3;

    // ---- Phase 1: build fg bitset ----
    const uint4* cls16 = (const uint4*)((const uint32_t*)g_cls + (size_t)t * (NPIX/4));
    uint32_t cpat = (uint32_t)c * 0x01010101u;
    for (int w = tid; w < 8192; w += FT) {
        uint4 a = cls16[w * 2];
        uint4 b = cls16[w * 2 + 1];
        uint32_t bits =  nib4(a.x, cpat)
                      | (nib4(a.y, cpat) << 4)
                      | (nib4(a.z, cpat) << 8)
                      | (nib4(a.w, cpat) << 12)
                      | (nib4(b.x, cpat) << 16)
                      | (nib4(b.y, cpat) << 20)
                      | (nib4(b.z, cpat) << 24)
                      | (nib4(b.w, cpat) << 28);
        int r = w >> 4, j = w & 15;
        fg[r * PITCH + j] = bits;
        fl[r * PITCH + j] = 0u;
    }
    if (tid == 0) s_bestkey = 0ull;
    __syncthreads();

    // ---- Phase 2: seed via bit-plane 5x5 counts; ONE row per thread ----
    unsigned long long mykey = 0ull;
    {
        int r = tid;
        const uint32_t* Grow = fg + r * PITCH;
        bool h2u = (r >= 2), h1u = (r >= 1);
        bool h1d = (r <= 510), h2d = (r <= 509);
        uint32_t V0[3], V1[3], V2[3];
        auto dovert = [&](int j, int s) {
            uint32_t a = h2u ? Grow[-2 * PITCH + j] : 0u;
            uint32_t b = h1u ? Grow[-1 * PITCH + j] : 0u;
            uint32_t cc = Grow[j];
            uint32_t d = h1d ? Grow[PITCH + j] : 0u;
            uint32_t e = h2d ? Grow[2 * PITCH + j] : 0u;
            uint32_t s1 = a ^ b ^ cc;
            uint32_t c1 = maj3(a, b, cc);
            uint32_t p0 = s1 ^ d ^ e;
            uint32_t c2 = maj3(s1, d, e);
            V0[s] = p0; V1[s] = c1 ^ c2; V2[s] = c1 & c2;
        };
        V0[0] = V1[0] = V2[0] = 0u;
        dovert(0, 1);
#pragma unroll 1
        for (int j = 0; j < 16; j++) {
            if (j < 15) dovert(j + 1, 2);
            else { V0[2] = V1[2] = V2[2] = 0u; }
            hwin_argmax(V0[0], V0[1], V0[2], V1[0], V1[1], V1[2],
                        V2[0], V2[1], V2[2], Grow[j], r, j, mykey);
            V0[0] = V0[1]; V1[0] = V1[1]; V2[0] = V2[1];
            V0[1] = V0[2]; V1[1] = V1[2]; V2[1] = V2[2];
        }
    }
#pragma unroll
    for (int off = 16; off; off >>= 1) {
        unsigned long long o = __shfl_down_sync(0xFFFFFFFFu, mykey, off);
        if (o > mykey) mykey = o;
    }
    if ((tid & 31) == 0 && mykey) atomicMax(&s_bestkey, mykey);
    __syncthreads();

    unsigned long long key = s_bestkey;
    double acc = 0.0;

    if (key != 0ull) {
        // ---- Phase 3: flood fill — WARP 0 ONLY, barrier-free loop ----
        if (tid < 32) {
            int lane = tid;
            int sidx = 0x3FFFF - (int)(key & 0x3FFFFull);
            int sr = sidx >> 9, scw = (sidx & 511) >> 5;
            if (lane == 0)
                fl[sr * PITCH + scw] = 1u << (sidx & 31);
            __syncwarp();

            int r0b = sr, r1b = sr, c0b = scw, c1b = scw;
            for (;;) {
                int er0 = r0b > 0   ? r0b - 1 : 0;
                int er1 = r1b < 511 ? r1b + 1 : 511;
                int wlo = c0b > 0   ? c0b - 1 : 0;
                int whi = c1b < 15 ? c1b + 1 : 15;
                bool narrow = (whi - wlo) <= 3;
                int base = wlo < 12 ? wlo : 12;
                bool ch = false;
                int myr0 = 1 << 30, myr1 = -1, myc0 = 16, myc1 = -1;
                for (int r = er0 + lane; r <= er1; r += 32) {
                    uint32_t* F = fl + r * PITCH;
                    const uint32_t* G = fg + r * PITCH;
                    bool hU = (r > 0), hD = (r < 511);
                    const uint32_t* U = F - PITCH;
                    const uint32_t* D = F + PITCH;
                    if (narrow) {
                        uint32_t S4[4], G4[4], F4[4];
                        uint32_t Vp = 0;
                        uint32_t Vc = (hU ? U[base] : 0u) | (hD ? D[base] : 0u);
#pragma unroll
                        for (int k = 0; k < 4; k++) {
                            int j = base + k;
                            uint32_t Vn = (k < 3)
                                ? ((hU ? U[j+1] : 0u) | (hD ? D[j+1] : 0u)) : 0u;
                            G4[k] = G[j];
                            F4[k] = F[j];
                            uint32_t vd = Vc | (Vc << 1) | (Vp >> 31)
                                             | (Vc >> 1) | (Vn << 31);
                            S4[k] = F4[k] | (vd & G4[k]);
                            Vp = Vc; Vc = Vn;
                        }
                        uint32_t carry = 0;
#pragma unroll
                        for (int k = 0; k < 4; k++) {
                            uint32_t s = S4[k] | (carry & G4[k] & 1u);
                            uint32_t cl = word_closure(G4[k], s);
                            S4[k] = cl; carry = cl >> 31;
                        }
                        carry = 0;
                        uint32_t dm = 0;
#pragma unroll
                        for (int k = 3; k >= 0; k--) {
                            uint32_t s = S4[k] | ((0u - carry) & G4[k] & 0x80000000u);
                            uint32_t cl = word_closure(G4[k], s);
                            S4[k] = cl; carry = cl & 1u;
                            if (cl != F4[k]) dm |= 1u << k;
                        }
                        if (dm) {
#pragma unroll
                            for (int k = 0; k < 4; k++)
                                if (dm & (1u << k)) F[base + k] = S4[k];
                            ch = true;
                            if (r < myr0) myr0 = r;
                            if (r > myr1) myr1 = r;
                            int lo = base + (__ffs(dm) - 1);
                            int hi = base + (31 - __clz(dm));
                            if (lo < myc0) myc0 = lo;
                            if (hi > myc1) myc1 = hi;
                        }
                    } else {
                        uint32_t S[16], Gw[16], Fo[16];
                        uint32_t Vp = 0;
                        uint32_t Vc = (hU ? U[0] : 0u) | (hD ? D[0] : 0u);
#pragma unroll
                        for (int j = 0; j < 16; j++) {
                            uint32_t Vn = (j < 15)
                                ? ((hU ? U[j+1] : 0u) | (hD ? D[j+1] : 0u)) : 0u;
                            Gw[j] = G[j];
                            Fo[j] = F[j];
                            uint32_t vd = Vc | (Vc << 1) | (Vp >> 31)
                                             | (Vc >> 1) | (Vn << 31);
                            S[j] = Fo[j] | (vd & Gw[j]);
                            Vp = Vc; Vc = Vn;
                        }
                        uint32_t carry = 0;
#pragma unroll
                        for (int j = 0; j < 16; j++) {
                            uint32_t s = S[j] | (carry & Gw[j] & 1u);
                            uint32_t cl = word_closure(Gw[j], s);
                            S[j] = cl; carry = cl >> 31;
                        }
                        carry = 0;
                        uint32_t dm = 0;
#pragma unroll
                        for (int j = 15; j >= 0; j--) {
                            uint32_t s = S[j] | ((0u - carry) & Gw[j] & 0x80000000u);
                            uint32_t cl = word_closure(Gw[j], s);
                            S[j] = cl; carry = cl & 1u;
                            if (cl != Fo[j]) dm |= 1u << j;
                        }
                        if (dm) {
#pragma unroll
                            for (int j = 0; j < 16; j++)
                                if (dm & (1u << j)) F[j] = S[j];
                            ch = true;
                            if (r < myr0) myr0 = r;
                            if (r > myr1) myr1 = r;
                            int lo = __ffs(dm) - 1;
                            int hi = 31 - __clz(dm);
                            if (lo < myc0) myc0 = lo;
                            if (hi > myc1) myc1 = hi;
                        }
                    }
                }
                unsigned any = __ballot_sync(0xFFFFFFFFu, ch);
                if (!any) break;
                myr0 = __reduce_min_sync(0xFFFFFFFFu, myr0);
                myr1 = __reduce_max_sync(0xFFFFFFFFu, myr1);
                myc0 = __reduce_min_sync(0xFFFFFFFFu, myc0);
                myc1 = __reduce_max_sync(0xFFFFFFFFu, myc1);
                if (myr0 < r0b) r0b = myr0;
                if (myr1 > r1b) r1b = myr1;
                if (myc0 < c0b) c0b = myc0;
                if (myc1 > c1b) c1b = myc1;
                __syncwarp();
            }
            if (lane == 0) {
                s_r0 = r0b; s_r1 = r1b; s_c0 = c0b; s_c1 = c1b;
            }
        }
        __syncthreads();

        // component log-prob sum over row+column bbox — division-free:
        // threads stride over (row, word) pairs via explicit carry loop.
        const float* pb = preds + ((size_t)(n * 4 + c) << 18);
        int c0 = s_c0, wc = s_c1 - s_c0 + 1;
        int r0 = s_r0, nrows = s_r1 - s_r0 + 1;
        int total = nrows * wc;
        // starting (row, col) for this thread without division: wc <= 16 so
        // tid/wc fits a small loop; advance by FT each step with carry.
        int q = 0, rm = tid;
        while (rm >= wc) { rm -= wc; q++; }          // q = tid/wc, rm = tid%wc
        int stepq = 0, steprm = FT;
        while (steprm >= wc) { steprm -= wc; stepq++; }
        for (int i = tid; i < total; i += FT) {
            int r = r0 + q, j = c0 + rm;
            uint32_t m = fl[r * PITCH + j];
            int bb = (r << 9) | (j << 5);
            while (m) {
                int b = __ffs(m) - 1;
                m &= m - 1;
                float p = pb[bb + b];
                acc += (double)logf(p + 1e-16f);
            }
            q += stepq; rm += steprm;
            if (rm >= wc) { rm -= wc; q++; }
        }
    }

    // per-CTA reduction (fixed tree) + last-CTA final loss
#pragma unroll
    for (int off = 16; off; off >>= 1)
        acc += __shfl_down_sync(0xFFFFFFFFu, acc, off);
    if ((tid & 31) == 0) s_red[tid >> 5] = acc;
    __syncthreads();
    if (tid == 0) {
        double tt = 0.0;
#pragma unroll
        for (int i = 0; i < FT / 32; i++) tt += s_red[i];
        g_partial[task] = tt;
        __threadfence();
        int old = atomicAdd(&g_done, 1);
        s_last = (old == NTASK * 3 - 1);
    }
    __syncthreads();

    if (s_last) {
        __threadfence();
        double v = (tid < NTASK * 3) ? g_partial[tid] : 0.0;
#pragma unroll
        for (int off = 16; off; off >>= 1)
            v += __shfl_down_sync(0xFFFFFFFFu, v, off);
        if ((tid & 31) == 0) s_red[tid >> 5] = v;
        __syncthreads();
        if (tid == 0) {
            double s = 0.0;
#pragma unroll
            for (int i = 0; i < FT / 32; i++) s += s_red[i];
            out[0] = (float)(-s / (double)TOTPIX);
        }
    }
}

// ---------------------------------------------------------------------------
extern "C" void kernel_launch(void* const* d_in, const int* in_sizes, int n_in,
                              void* d_out, int out_size) {
    (void)in_sizes; (void)n_in; (void)out_size;
    const float* preds = (const float*)d_in[0];
    float* out = (float*)d_out;

    int smem = 2 * 512 * PITCH * (int)sizeof(uint32_t);   // 69632 B
    cudaFuncSetAttribute(k_flood, cudaFuncAttributeMaxDynamicSharedMemorySize, smem);

    k_sample<<<(TOTPIX + 255) / 256, 256>>>(preds);
    k_flood<<<NTASK * 3, FT, smem>>>(preds, out);
}

// round 16
// speedup vs baseline: 1.0914x; 1.0914x over previous
#include <cuda_runtime.h>
#include <cstdint>

// ===========================================================================
// reinforce_cons_loss (2-kernel pipeline) — converged best (round-13 form):
//   K1 Threefry-2x32 Gumbel-max categorical sampling (at alu-pipe floor)
//   K2 (512 thr/CTA) per-(task,class): fg bitset; in-CTA 5x5-count argmax
//      seed (bit-plane CSA, 1 row/thread); flood fill on WARP 0 ONLY —
//      barrier-free H-closure iterations (ballot convergence, redux bbox),
//      row+col bbox restriction, 4-word narrow fast path; log-prob sum;
//      last-CTA final loss reduction.
// ===========================================================================

#define NIMG   4
#define NSAMP  10
#define HH     512
#define WW     512
#define NTASK  (NIMG*NSAMP)
#define NPIX   (HH*WW)                 // 1<<18
#define TOTPIX ((unsigned)NTASK*NPIX)  // 10485760
#define PITCH  17
#define FT     512

__device__ uint8_t g_cls[(size_t)NTASK * NPIX];
__device__ double  g_partial[NTASK * 3];
__device__ int     g_done;

// ---------------------------------------------------------------------------
// Threefry-2x32, 20 rounds, key (0,42), counter (0, idx); out = x0 ^ x1
// ---------------------------------------------------------------------------
#define TF_ROUND(x0,x1,R) { x0 += x1; x1 = __funnelshift_l(x1, x1, (R)); x1 ^= x0; }

__device__ __forceinline__ uint32_t gumbel_bits(uint32_t idx) {
    const uint32_t k0 = 0u, k1 = 42u;
    const uint32_t k2 = k0 ^ k1 ^ 0x1BD11BDAu;
    uint32_t x0 = k0, x1 = idx + k1;
    TF_ROUND(x0,x1,13) TF_ROUND(x0,x1,15) TF_ROUND(x0,x1,26) TF_ROUND(x0,x1,6)
    x0 += k1; x1 += k2 + 1u;
    TF_ROUND(x0,x1,17) TF_ROUND(x0,x1,29) TF_ROUND(x0,x1,16) TF_ROUND(x0,x1,24)
    x0 += k2; x1 += k0 + 2u;
    TF_ROUND(x0,x1,13) TF_ROUND(x0,x1,15) TF_ROUND(x0,x1,26) TF_ROUND(x0,x1,6)
    x0 += k0; x1 += k1 + 3u;
    TF_ROUND(x0,x1,17) TF_ROUND(x0,x1,29) TF_ROUND(x0,x1,16) TF_ROUND(x0,x1,24)
    x0 += k1; x1 += k2 + 4u;
    TF_ROUND(x0,x1,13) TF_ROUND(x0,x1,15) TF_ROUND(x0,x1,26) TF_ROUND(x0,x1,6)
    x0 += k2; x1 += k0 + 5u;
    return x0 ^ x1;
}

__device__ __forceinline__ float bits_to_u(uint32_t bits) {
    const float tiny = 1.17549435082228751e-38f;
    float f = __uint_as_float(__umulhi(bits, 0x00800000u) + 0x3f800000u) - 1.0f;
    return fmaxf(f, tiny);
}

// ---------------------------------------------------------------------------
// K1: gumbel-max, product form argmax_c p_c / (-log2 u_c); MUFU fast path
//     with precise-log fallback on near-ties.
// ---------------------------------------------------------------------------
__global__ void __launch_bounds__(256) k_sample(const float* __restrict__ preds) {
    unsigned gid = blockIdx.x * 256u + threadIdx.x;
    if (blockIdx.x == 0 && threadIdx.x == 0) g_done = 0;
    if (gid >= TOTPIX) return;
    unsigned hw = gid & 0x3FFFFu;
    unsigned n  = (gid >> 18) & 3u;
    const float* pb = preds + ((size_t)n << 20) + hw;

    float p0 = pb[0];
    float p1 = pb[(size_t)1 << 18];
    float p2 = pb[(size_t)2 << 18];
    float p3 = pb[(size_t)3 << 18];

    unsigned base = gid << 2;
    float u0 = bits_to_u(gumbel_bits(base + 0));
    float u1 = bits_to_u(gumbel_bits(base + 1));
    float u2 = bits_to_u(gumbel_bits(base + 2));
    float u3 = bits_to_u(gumbel_bits(base + 3));

    float w0 = -__log2f(u0);
    float w1 = -__log2f(u1);
    float w2 = -__log2f(u2);
    float w3 = -__log2f(u3);

    float bp = p0, bw = w0; unsigned bc = 0;
    bool risky = false;
    {
        float lhs = p1 * bw, rhs = bp * w1;
        risky |= fabsf(lhs - rhs) <= 2e-6f + 2e-6f * (lhs + rhs);
        if (lhs > rhs) { bp = p1; bw = w1; bc = 1; }
    }
    {
        float lhs = p2 * bw, rhs = bp * w2;
        risky |= fabsf(lhs - rhs) <= 2e-6f + 2e-6f * (lhs + rhs);
        if (lhs > rhs) { bp = p2; bw = w2; bc = 2; }
    }
    {
        float lhs = p3 * bw, rhs = bp * w3;
        risky |= fabsf(lhs - rhs) <= 2e-6f + 2e-6f * (lhs + rhs);
        if (lhs > rhs) { bp = p3; bw = w3; bc = 3; }
    }
    if (risky) {
        w0 = -log2f(u0);
        w1 = -log2f(u1);
        w2 = -log2f(u2);
        w3 = -log2f(u3);
        bp = p0; bw = w0; bc = 0;
        if (p1 * bw > bp * w1) { bp = p1; bw = w1; bc = 1; }
        if (p2 * bw > bp * w2) { bp = p2; bw = w2; bc = 2; }
        if (p3 * bw > bp * w3) { bp = p3; bw = w3; bc = 3; }
    }
    g_cls[gid] = (uint8_t)bc;
}

// ---------------------------------------------------------------------------
// K2 helpers
// ---------------------------------------------------------------------------
__device__ __forceinline__ uint32_t word_closure(uint32_t g, uint32_t s) {
    uint32_t up = g & ~(g + s);
    uint32_t gr = __brev(g), sr = __brev(s);
    uint32_t dn = __brev(gr & ~(gr + sr));
    return s | up | dn;
}

__device__ __forceinline__ uint32_t nib4(uint32_t v, uint32_t cpat) {
    uint32_t eq = __vcmpeq4(v, cpat);
    return ((eq & 0x01010101u) * 0x01020408u) >> 24;
}

__device__ __forceinline__ uint32_t maj3(uint32_t a, uint32_t b, uint32_t c) {
    return (a & b) | (a & c) | (b & c);
}

__device__ __forceinline__ void hwin_argmax(
        uint32_t P0p, uint32_t P0c, uint32_t P0n,
        uint32_t P1p, uint32_t P1c, uint32_t P1n,
        uint32_t P2p, uint32_t P2c, uint32_t P2n,
        uint32_t m, int r, int j, unsigned long long& mykey) {
    if (!m) return;
    uint32_t n1_0 = __funnelshift_l(P0p, P0c, 2);
    uint32_t n1_1 = __funnelshift_l(P1p, P1c, 2);
    uint32_t n1_2 = __funnelshift_l(P2p, P2c, 2);
    uint32_t n2_0 = __funnelshift_l(P0p, P0c, 1);
    uint32_t n2_1 = __funnelshift_l(P1p, P1c, 1);
    uint32_t n2_2 = __funnelshift_l(P2p, P2c, 1);
    uint32_t n4_0 = __funnelshift_r(P0c, P0n, 1);
    uint32_t n4_1 = __funnelshift_r(P1c, P1n, 1);
    uint32_t n4_2 = __funnelshift_r(P2c, P2n, 1);
    uint32_t n5_0 = __funnelshift_r(P0c, P0n, 2);
    uint32_t n5_1 = __funnelshift_r(P1c, P1n, 2);
    uint32_t n5_2 = __funnelshift_r(P2c, P2n, 2);
    uint32_t s0 = n1_0 ^ n2_0 ^ P0c, a1 = maj3(n1_0, n2_0, P0c);
    uint32_t s1 = n1_1 ^ n2_1 ^ P1c, a2 = maj3(n1_1, n2_1, P1c);
    uint32_t s2 = n1_2 ^ n2_2 ^ P2c, a3 = maj3(n1_2, n2_2, P2c);
    uint32_t t0 = s0 ^ n4_0,         c1a = s0 & n4_0;
    uint32_t t1 = s1 ^ a1 ^ n4_1,    c2a = maj3(s1, a1, n4_1);
    uint32_t t2 = s2 ^ a2 ^ n4_2,    c3a = maj3(s2, a2, n4_2);
    uint32_t t3 = a3;
    uint32_t u0 = t0 ^ n5_0,         d1 = t0 & n5_0;
    uint32_t u1 = t1 ^ c1a ^ n5_1,   d2 = maj3(t1, c1a, n5_1);
    uint32_t u2 = t2 ^ c2a ^ n5_2,   d3 = maj3(t2, c2a, n5_2);
    uint32_t u3 = t3 ^ c3a,          d4 = t3 & c3a;
    uint32_t H0 = u0;
    uint32_t H1 = u1 ^ d1,           e1 = u1 & d1;
    uint32_t H2 = u2 ^ d2 ^ e1,      e2 = maj3(u2, d2, e1);
    uint32_t H3 = u3 ^ d3 ^ e2,      e3 = maj3(u3, d3, e2);
    uint32_t H4 = d4 ^ e3;
    uint32_t M = 0, tt;
    tt = m & H4; if (tt) { m = tt; M += 16u; }
    tt = m & H3; if (tt) { m = tt; M += 8u; }
    tt = m & H2; if (tt) { m = tt; M += 4u; }
    tt = m & H1; if (tt) { m = tt; M += 2u; }
    tt = m & H0; if (tt) { m = tt; M += 1u; }
    unsigned idx = ((unsigned)r << 9) | ((unsigned)j << 5)
                 | (unsigned)(__ffs(m) - 1);
    unsigned long long key = ((unsigned long long)M << 18) |
                             (unsigned long long)(0x3FFFFu - idx);
    if (key > mykey) mykey = key;
}

// ---------------------------------------------------------------------------
// K2: one CTA (512 thr) per (task, class).
// ---------------------------------------------------------------------------
__global__ void __launch_bounds__(FT) k_flood(const float* __restrict__ preds,
                                              float* __restrict__ out) {
    extern __shared__ uint32_t sm[];
    uint32_t* fg = sm;                 // 512*17 words
    uint32_t* fl = sm + 512 * PITCH;   // 512*17 words
    __shared__ int s_r0, s_r1, s_c0, s_c1;
    __shared__ double s_red[FT / 32];
    __shared__ int s_last;
    __shared__ unsigned long long s_bestkey;

    int tid  = threadIdx.x;
    int task = blockIdx.x;
    int t = task / 3;
    int c = task % 3 + 1;
    int n = t & 3;

    // ---- Phase 1: build fg bitset ----
    const uint4* cls16 = (const uint4*)((const uint32_t*)g_cls + (size_t)t * (NPIX/4));
    uint32_t cpat = (uint32_t)c * 0x01010101u;
    for (int w = tid; w < 8192; w += FT) {
        uint4 a = cls16[w * 2];
        uint4 b = cls16[w * 2 + 1];
        uint32_t bits =  nib4(a.x, cpat)
                      | (nib4(a.y, cpat) << 4)
                      | (nib4(a.z, cpat) << 8)
                      | (nib4(a.w, cpat) << 12)
                      | (nib4(b.x, cpat) << 16)
                      | (nib4(b.y, cpat) << 20)
                      | (nib4(b.z, cpat) << 24)
                      | (nib4(b.w, cpat) << 28);
        int r = w >> 4, j = w & 15;
        fg[r * PITCH + j] = bits;
        fl[r * PITCH + j] = 0u;
    }
    if (tid == 0) s_bestkey = 0ull;
    __syncthreads();

    // ---- Phase 2: seed via bit-plane 5x5 counts; ONE row per thread ----
    unsigned long long mykey = 0ull;
    {
        int r = tid;
        const uint32_t* Grow = fg + r * PITCH;
        bool h2u = (r >= 2), h1u = (r >= 1);
        bool h1d = (r <= 510), h2d = (r <= 509);
        uint32_t V0[3], V1[3], V2[3];
        auto dovert = [&](int j, int s) {
            uint32_t a = h2u ? Grow[-2 * PITCH + j] : 0u;
            uint32_t b = h1u ? Grow[-1 * PITCH + j] : 0u;
            uint32_t cc = Grow[j];
            uint32_t d = h1d ? Grow[PITCH + j] : 0u;
            uint32_t e = h2d ? Grow[2 * PITCH + j] : 0u;
            uint32_t s1 = a ^ b ^ cc;
            uint32_t c1 = maj3(a, b, cc);
            uint32_t p0 = s1 ^ d ^ e;
            uint32_t c2 = maj3(s1, d, e);
            V0[s] = p0; V1[s] = c1 ^ c2; V2[s] = c1 & c2;
        };
        V0[0] = V1[0] = V2[0] = 0u;
        dovert(0, 1);
#pragma unroll 1
        for (int j = 0; j < 16; j++) {
            if (j < 15) dovert(j + 1, 2);
            else { V0[2] = V1[2] = V2[2] = 0u; }
            hwin_argmax(V0[0], V0[1], V0[2], V1[0], V1[1], V1[2],
                        V2[0], V2[1], V2[2], Grow[j], r, j, mykey);
            V0[0] = V0[1]; V1[0] = V1[1]; V2[0] = V2[1];
            V0[1] = V0[2]; V1[1] = V1[2]; V2[1] = V2[2];
        }
    }
#pragma unroll
    for (int off = 16; off; off >>= 1) {
        unsigned long long o = __shfl_down_sync(0xFFFFFFFFu, mykey, off);
        if (o > mykey) mykey = o;
    }
    if ((tid & 31) == 0 && mykey) atomicMax(&s_bestkey, mykey);
    __syncthreads();

    unsigned long long key = s_bestkey;
    double acc = 0.0;

    if (key != 0ull) {
        // ---- Phase 3: flood fill — WARP 0 ONLY, barrier-free loop ----
        if (tid < 32) {
            int lane = tid;
            int sidx = 0x3FFFF - (int)(key & 0x3FFFFull);
            int sr = sidx >> 9, scw = (sidx & 511) >> 5;
            if (lane == 0)
                fl[sr * PITCH + scw] = 1u << (sidx & 31);
            __syncwarp();

            int r0b = sr, r1b = sr, c0b = scw, c1b = scw;
            for (;;) {
                int er0 = r0b > 0   ? r0b - 1 : 0;
                int er1 = r1b < 511 ? r1b + 1 : 511;
                int wlo = c0b > 0   ? c0b - 1 : 0;
                int whi = c1b < 15 ? c1b + 1 : 15;
                bool narrow = (whi - wlo) <= 3;
                int base = wlo < 12 ? wlo : 12;
                bool ch = false;
                int myr0 = 1 << 30, myr1 = -1, myc0 = 16, myc1 = -1;
                for (int r = er0 + lane; r <= er1; r += 32) {
                    uint32_t* F = fl + r * PITCH;
                    const uint32_t* G = fg + r * PITCH;
                    bool hU = (r > 0), hD = (r < 511);
                    const uint32_t* U = F - PITCH;
                    const uint32_t* D = F + PITCH;
                    if (narrow) {
                        uint32_t S4[4], G4[4], F4[4];
                        uint32_t Vp = 0;
                        uint32_t Vc = (hU ? U[base] : 0u) | (hD ? D[base] : 0u);
#pragma unroll
                        for (int k = 0; k < 4; k++) {
                            int j = base + k;
                            uint32_t Vn = (k < 3)
                                ? ((hU ? U[j+1] : 0u) | (hD ? D[j+1] : 0u)) : 0u;
                            G4[k] = G[j];
                            F4[k] = F[j];
                            uint32_t vd = Vc | (Vc << 1) | (Vp >> 31)
                                             | (Vc >> 1) | (Vn << 31);
                            S4[k] = F4[k] | (vd & G4[k]);
                            Vp = Vc; Vc = Vn;
                        }
                        uint32_t carry = 0;
#pragma unroll
                        for (int k = 0; k < 4; k++) {
                            uint32_t s = S4[k] | (carry & G4[k] & 1u);
                            uint32_t cl = word_closure(G4[k], s);
                            S4[k] = cl; carry = cl >> 31;
                        }
                        carry = 0;
                        uint32_t dm = 0;
#pragma unroll
                        for (int k = 3; k >= 0; k--) {
                            uint32_t s = S4[k] | ((0u - carry) & G4[k] & 0x80000000u);
                            uint32_t cl = word_closure(G4[k], s);
                            S4[k] = cl; carry = cl & 1u;
                            if (cl != F4[k]) dm |= 1u << k;
                        }
                        if (dm) {
#pragma unroll
                            for (int k = 0; k < 4; k++)
                                if (dm & (1u << k)) F[base + k] = S4[k];
                            ch = true;
                            if (r < myr0) myr0 = r;
                            if (r > myr1) myr1 = r;
                            int lo = base + (__ffs(dm) - 1);
                            int hi = base + (31 - __clz(dm));
                            if (lo < myc0) myc0 = lo;
                            if (hi > myc1) myc1 = hi;
                        }
                    } else {
                        uint32_t S[16], Gw[16], Fo[16];
                        uint32_t Vp = 0;
                        uint32_t Vc = (hU ? U[0] : 0u) | (hD ? D[0] : 0u);
#pragma unroll
                        for (int j = 0; j < 16; j++) {
                            uint32_t Vn = (j < 15)
                                ? ((hU ? U[j+1] : 0u) | (hD ? D[j+1] : 0u)) : 0u;
                            Gw[j] = G[j];
                            Fo[j] = F[j];
                            uint32_t vd = Vc | (Vc << 1) | (Vp >> 31)
                                             | (Vc >> 1) | (Vn << 31);
                            S[j] = Fo[j] | (vd & Gw[j]);
                            Vp = Vc; Vc = Vn;
                        }
                        uint32_t carry = 0;
#pragma unroll
                        for (int j = 0; j < 16; j++) {
                            uint32_t s = S[j] | (carry & Gw[j] & 1u);
                            uint32_t cl = word_closure(Gw[j], s);
                            S[j] = cl; carry = cl >> 31;
                        }
                        carry = 0;
                        uint32_t dm = 0;
#pragma unroll
                        for (int j = 15; j >= 0; j--) {
                            uint32_t s = S[j] | ((0u - carry) & Gw[j] & 0x80000000u);
                            uint32_t cl = word_closure(Gw[j], s);
                            S[j] = cl; carry = cl & 1u;
                            if (cl != Fo[j]) dm |= 1u << j;
                        }
                        if (dm) {
#pragma unroll
                            for (int j = 0; j < 16; j++)
                                if (dm & (1u << j)) F[j] = S[j];
                            ch = true;
                            if (r < myr0) myr0 = r;
                            if (r > myr1) myr1 = r;
                            int lo = __ffs(dm) - 1;
                            int hi = 31 - __clz(dm);
                            if (lo < myc0) myc0 = lo;
                            if (hi > myc1) myc1 = hi;
                        }
                    }
                }
                unsigned any = __ballot_sync(0xFFFFFFFFu, ch);
                if (!any) break;
                myr0 = __reduce_min_sync(0xFFFFFFFFu, myr0);
                myr1 = __reduce_max_sync(0xFFFFFFFFu, myr1);
                myc0 = __reduce_min_sync(0xFFFFFFFFu, myc0);
                myc1 = __reduce_max_sync(0xFFFFFFFFu, myc1);
                if (myr0 < r0b) r0b = myr0;
                if (myr1 > r1b) r1b = myr1;
                if (myc0 < c0b) c0b = myc0;
                if (myc1 > c1b) c1b = myc1;
                __syncwarp();
            }
            if (lane == 0) {
                s_r0 = r0b; s_r1 = r1b; s_c0 = c0b; s_c1 = c1b;
            }
        }
        __syncthreads();

        // component log-prob sum over row+column bbox (all threads)
        const float* pb = preds + ((size_t)(n * 4 + c) << 18);
        int c0 = s_c0, wc = s_c1 - s_c0 + 1;
        int nw = (s_r1 - s_r0 + 1) * wc;
        for (int i = tid; i < nw; i += FT) {
            int r = s_r0 + i / wc, j = c0 + i % wc;
            uint32_t m = fl[r * PITCH + j];
            int bb = (r << 9) | (j << 5);
            while (m) {
                int b = __ffs(m) - 1;
                m &= m - 1;
                float p = pb[bb + b];
                acc += (double)logf(p + 1e-16f);
            }
        }
    }

    // per-CTA reduction (fixed tree) + last-CTA final loss
#pragma unroll
    for (int off = 16; off; off >>= 1)
        acc += __shfl_down_sync(0xFFFFFFFFu, acc, off);
    if ((tid & 31) == 0) s_red[tid >> 5] = acc;
    __syncthreads();
    if (tid == 0) {
        double tt = 0.0;
#pragma unroll
        for (int i = 0; i < FT / 32; i++) tt += s_red[i];
        g_partial[task] = tt;
        __threadfence();
        int old = atomicAdd(&g_done, 1);
        s_last = (old == NTASK * 3 - 1);
    }
    __syncthreads();

    if (s_last) {
        __threadfence();
        double v = (tid < NTASK * 3) ? g_partial[tid] : 0.0;
#pragma unroll
        for (int off = 16; off; off >>= 1)
            v += __shfl_down_sync(0xFFFFFFFFu, v, off);
        if ((tid & 31) == 0) s_red[tid >> 5] = v;
        __syncthreads();
        if (tid == 0) {
            double s = 0.0;
#pragma unroll
            for (int i = 0; i < FT / 32; i++) s += s_red[i];
            out[0] = (float)(-s / (double)TOTPIX);
        }
    }
}

// ---------------------------------------------------------------------------
extern "C" void kernel_launch(void* const* d_in, const int* in_sizes, int n_in,
                              void* d_out, int out_size) {
    (void)in_sizes; (void)n_in; (void)out_size;
    const float* preds = (const float*)d_in[0];
    float* out = (float*)d_out;

    int smem = 2 * 512 * PITCH * (int)sizeof(uint32_t);   // 69632 B
    cudaFuncSetAttribute(k_flood, cudaFuncAttributeMaxDynamicSharedMemorySize, smem);

    k_sample<<<(TOTPIX + 255) / 256, 256>>>(preds);
    k_flood<<<NTASK * 3, FT, smem>>>(preds, out);
}